// round 8
// baseline (speedup 1.0000x reference)
#include <cuda_runtime.h>
#include <cuda_bf16.h>
#include <cstdint>

// B=16, TQ=TP=DQ=DP=1024
// out = softmax_over_Tp((p@W)@q^T) @ q, fp32 in/out.
// GEMMs: mma.sync.m16n8k16 bf16, 2-way split, 3 products (hh+hl+lh).
// Warp-specialized: 8 consumer warps (64x32 tiles) + 2 loader warps,
// 6-stage cp.async pipeline with mbarrier handoff (no CTA barrier in mainloop).

static const long TT = 1048576L;

// ---------------- scratch ----------------
__device__ __nv_bfloat16 g_qhi[16777216], g_qlo[16777216];
__device__ __nv_bfloat16 g_phi[16777216], g_plo[16777216];
__device__ __nv_bfloat16 g_qThi[16777216], g_qTlo[16777216];
__device__ __nv_bfloat16 g_Wthi[1048576],  g_Wtlo[1048576];
__device__ __nv_bfloat16 g_pWhi[16777216], g_pWlo[16777216];
__device__ __nv_bfloat16 g_Ehi[16777216],  g_Elo[16777216];
__device__ float g_S[16777216];

// ---------------- asm helpers ----------------
__device__ __forceinline__ uint32_t smem_u32(const void* p) {
    uint32_t a;
    asm("{ .reg .u64 t; cvta.to.shared.u64 t, %1; cvt.u32.u64 %0, t; }" : "=r"(a) : "l"(p));
    return a;
}
__device__ __forceinline__ void cp16(uint32_t s, const void* g) {
    asm volatile("cp.async.cg.shared.global [%0], [%1], 16;" :: "r"(s), "l"(g));
}
__device__ __forceinline__ void ldsm4(uint32_t (&r)[4], uint32_t a) {
    asm volatile("ldmatrix.sync.aligned.m8n8.x4.shared.b16 {%0,%1,%2,%3}, [%4];"
                 : "=r"(r[0]), "=r"(r[1]), "=r"(r[2]), "=r"(r[3]) : "r"(a));
}
__device__ __forceinline__ void mma16816(float (&d)[4], const uint32_t (&a)[4],
                                         uint32_t b0, uint32_t b1) {
    asm volatile(
        "mma.sync.aligned.m16n8k16.row.col.f32.bf16.bf16.f32 "
        "{%0,%1,%2,%3}, {%4,%5,%6,%7}, {%8,%9}, {%0,%1,%2,%3};"
        : "+f"(d[0]), "+f"(d[1]), "+f"(d[2]), "+f"(d[3])
        : "r"(a[0]), "r"(a[1]), "r"(a[2]), "r"(a[3]), "r"(b0), "r"(b1));
}

#define MBARRIER_INIT(mbar, count) \
    asm volatile("mbarrier.init.shared.b64 [%0], %1;" :: "r"((uint32_t)(mbar)), "r"((uint32_t)(count)) : "memory")
#define MBARRIER_ARRIVE(mbar) \
    asm volatile("mbarrier.arrive.shared.b64 _, [%0];" :: "r"((uint32_t)(mbar)) : "memory")
#define CPASYNC_MBAR_ARRIVE(mbar) \
    asm volatile("cp.async.mbarrier.arrive.noinc.shared.b64 [%0];" :: "r"((uint32_t)(mbar)) : "memory")

#define MBARRIER_WAIT_PARITY(mbar_smem_addr, phase_parity) do { \
    uint32_t _mbar = (uint32_t)(mbar_smem_addr); \
    uint32_t _parity = (uint32_t)(phase_parity); \
    uint32_t _done; \
    asm volatile( \
        "{\n\t.reg .pred p;\n\t" \
        "mbarrier.try_wait.parity.acquire.cta.shared::cta.b64 p, [%1], %2;\n\t" \
        "selp.b32 %0, 1, 0, p;\n\t}" \
        : "=r"(_done) : "r"(_mbar), "r"(_parity) : "memory"); \
    if (!_done) { \
        asm volatile( \
            "{\n\t.reg .pred P1;\n\t" \
            "WAIT_LOOP_%=:\n\t" \
            "mbarrier.try_wait.parity.acquire.cta.shared::cta.b64 P1, [%0], %1, 0x989680;\n\t" \
            "@P1 bra.uni WAIT_DONE_%=;\n\t" \
            "bra.uni WAIT_LOOP_%=;\n\t" \
            "WAIT_DONE_%=:\n\t}" \
            :: "r"(_mbar), "r"(_parity) : "memory"); \
    } \
} while(0)

// ---------------- GEMM: C[b][m][n] = sum_k A[b][m][k] * B[b][n][k] ----------------
// Stage: A-tile 128 rows x [hi64B|lo64B] (16KB) + B-tile same (16KB) = 32KB, 6 stages.
static constexpr int MATB    = 128 * 128;     // 16KB packed hi/lo tile
static constexpr int STAGEB  = 2 * MATB;      // 32KB
static constexpr int NSTAGE  = 6;
static constexpr int SMEM_ST = 1024;          // stage data starts here (barriers below)
static constexpr int SMEMSZ  = SMEM_ST + NSTAGE * STAGEB;   // 1KB + 192KB

template<int STORE_SPLIT>
__global__ void __launch_bounds__(320, 1)
gemm_mma(const __nv_bfloat16* __restrict__ Ahi, const __nv_bfloat16* __restrict__ Alo, long sA,
         const __nv_bfloat16* __restrict__ Bhi, const __nv_bfloat16* __restrict__ Blo, long sB,
         float* __restrict__ Cf, __nv_bfloat16* __restrict__ Chi, __nv_bfloat16* __restrict__ Clo)
{
    extern __shared__ char smem[];
    const uint32_t sbase = smem_u32(smem);
    const int tid = threadIdx.x, lane = tid & 31, wid = tid >> 5;
    const int b = blockIdx.z, m0 = blockIdx.y * 128, n0 = blockIdx.x * 128;

    // mbarriers: full[s] at sbase + s*16, empty[s] at sbase + s*16 + 8
    if (tid == 0) {
        #pragma unroll
        for (int s = 0; s < NSTAGE; s++) {
            MBARRIER_INIT(sbase + s * 16,     64);  // full: 64 loader threads
            MBARRIER_INIT(sbase + s * 16 + 8, 8);   // empty: 8 consumer warps
        }
    }
    __syncthreads();

    if (wid >= 8) {
        // ---------------- loader warps (2 warps, 64 threads) ----------------
        const int lt = tid - 256;
        const char* gA[2] = { (const char*)(Ahi + (size_t)b * sA + (size_t)m0 * 1024),
                              (const char*)(Alo + (size_t)b * sA + (size_t)m0 * 1024) };
        const char* gB[2] = { (const char*)(Bhi + (size_t)b * sB + (size_t)n0 * 1024),
                              (const char*)(Blo + (size_t)b * sB + (size_t)n0 * 1024) };
        int st = 0, ph = 1;
        #pragma unroll 1
        for (int kt = 0; kt < 32; kt++) {
            MBARRIER_WAIT_PARITY(sbase + st * 16 + 8, ph);   // wait empty
            const uint32_t sb = sbase + SMEM_ST + st * STAGEB;
            const size_t kb = (size_t)kt * 64;
            #pragma unroll
            for (int m = 0; m < 2; m++) {
                const uint32_t mb = sb + m * MATB;
                #pragma unroll
                for (int hl = 0; hl < 2; hl++) {
                    const char* g = (m == 0) ? gA[hl] : gB[hl];
                    #pragma unroll
                    for (int t = 0; t < 2; t++) {
                        const int r = lt + t * 64;
                        #pragma unroll
                        for (int c = 0; c < 4; c++) {
                            cp16(mb + r * 128 + (((c + hl * 4) ^ (r & 7)) * 16),
                                 g + (size_t)r * 2048 + kb + c * 16);
                        }
                    }
                }
            }
            CPASYNC_MBAR_ARRIVE(sbase + st * 16);            // arrive full on completion
            if (++st == NSTAGE) { st = 0; ph ^= 1; }
        }
        return;
    }

    // ---------------- consumer warps (8 warps, 2m x 4n, 64x32 tiles) ----------------
    const int wm = wid >> 2, wn = wid & 3;

    float acc[4][4][4];
    #pragma unroll
    for (int i = 0; i < 4; i++)
        #pragma unroll
        for (int j = 0; j < 4; j++)
            #pragma unroll
            for (int t = 0; t < 4; t++) acc[i][j][t] = 0.f;

    const int lrow = lane & 15, lhi = lane >> 4;
    const int swz = lrow & 7;
    uint32_t kh[2], kl[2];
    #pragma unroll
    for (int ks = 0; ks < 2; ks++) {
        kh[ks] = (uint32_t)(((ks * 2 + lhi) ^ swz) * 16);
        kl[ks] = (uint32_t)(((ks * 2 + lhi + 4) ^ swz) * 16);
    }
    const uint32_t arow_off = (uint32_t)(wm * 64 + lrow) * 128;
    const uint32_t brow_off = (uint32_t)(wn * 32 + lrow) * 128;

    int st = 0, ph = 0;
    #pragma unroll 1
    for (int kt = 0; kt < 32; kt++) {
        MBARRIER_WAIT_PARITY(sbase + st * 16, ph);           // wait full
        const uint32_t sb = sbase + SMEM_ST + st * STAGEB;
        const uint32_t sA_ = sb, sB_ = sb + MATB;

        #pragma unroll
        for (int ks = 0; ks < 2; ks++) {
            const uint32_t kbh = kh[ks], kbl = kl[ks];
            // product 1: hh
            uint32_t ah[4][4];
            #pragma unroll
            for (int mi = 0; mi < 4; mi++)
                ldsm4(ah[mi], sA_ + arow_off + (uint32_t)(mi * 16) * 128 + kbh);
            uint32_t bh[4][2];
            #pragma unroll
            for (int nj = 0; nj < 2; nj++) {
                uint32_t r[4];
                ldsm4(r, sB_ + brow_off + (uint32_t)(nj * 16) * 128 + kbh);
                bh[2*nj][0] = r[0]; bh[2*nj+1][0] = r[1];
                bh[2*nj][1] = r[2]; bh[2*nj+1][1] = r[3];
            }
            #pragma unroll
            for (int mi = 0; mi < 4; mi++)
                #pragma unroll
                for (int ni = 0; ni < 4; ni++)
                    mma16816(acc[mi][ni], ah[mi], bh[ni][0], bh[ni][1]);
            // product 2: hl (reuse ah)
            uint32_t bl[4][2];
            #pragma unroll
            for (int nj = 0; nj < 2; nj++) {
                uint32_t r[4];
                ldsm4(r, sB_ + brow_off + (uint32_t)(nj * 16) * 128 + kbl);
                bl[2*nj][0] = r[0]; bl[2*nj+1][0] = r[1];
                bl[2*nj][1] = r[2]; bl[2*nj+1][1] = r[3];
            }
            #pragma unroll
            for (int mi = 0; mi < 4; mi++)
                #pragma unroll
                for (int ni = 0; ni < 4; ni++)
                    mma16816(acc[mi][ni], ah[mi], bl[ni][0], bl[ni][1]);
            // product 3: lh (reuse bh)
            uint32_t al[4][4];
            #pragma unroll
            for (int mi = 0; mi < 4; mi++)
                ldsm4(al[mi], sA_ + arow_off + (uint32_t)(mi * 16) * 128 + kbl);
            #pragma unroll
            for (int mi = 0; mi < 4; mi++)
                #pragma unroll
                for (int ni = 0; ni < 4; ni++)
                    mma16816(acc[mi][ni], al[mi], bh[ni][0], bh[ni][1]);
        }
        // release buffer: all HMMAs above have issued (so all ldsm completed)
        if (lane == 0) MBARRIER_ARRIVE(sbase + st * 16 + 8);
        if (++st == NSTAGE) { st = 0; ph ^= 1; }
    }

    // epilogue
    const int er = m0 + wm * 64 + (lane >> 2);
    const int ec = n0 + wn * 32 + (lane & 3) * 2;
    #pragma unroll
    for (int mi = 0; mi < 4; mi++)
        #pragma unroll
        for (int ni = 0; ni < 4; ni++) {
            const int r0 = er + mi * 16, c = ec + ni * 8;
            const size_t o0 = (size_t)b * TT + (size_t)r0 * 1024 + c;
            const size_t o1 = o0 + 8 * 1024;
            if (STORE_SPLIT == 0) {
                *(float2*)(Cf + o0) = make_float2(acc[mi][ni][0], acc[mi][ni][1]);
                *(float2*)(Cf + o1) = make_float2(acc[mi][ni][2], acc[mi][ni][3]);
            } else {
                #pragma unroll
                for (int h = 0; h < 2; h++) {
                    const size_t o = h ? o1 : o0;
                    float x0 = acc[mi][ni][2*h], x1 = acc[mi][ni][2*h+1];
                    __nv_bfloat16 h0 = __float2bfloat16(x0);
                    __nv_bfloat16 h1 = __float2bfloat16(x1);
                    __nv_bfloat16 l0 = __float2bfloat16(x0 - __bfloat162float(h0));
                    __nv_bfloat16 l1 = __float2bfloat16(x1 - __bfloat162float(h1));
                    __nv_bfloat162 hp; hp.x = h0; hp.y = h1;
                    __nv_bfloat162 lp; lp.x = l0; lp.y = l1;
                    *(__nv_bfloat162*)(Chi + o) = hp;
                    *(__nv_bfloat162*)(Clo + o) = lp;
                }
            }
        }
}

// ---------------- elementwise / transpose / softmax ----------------
struct alignas(8) bh4 { __nv_bfloat16 a, b, c, d; };

__device__ __forceinline__ void split1(float x, __nv_bfloat16& h, __nv_bfloat16& l) {
    h = __float2bfloat16(x);
    l = __float2bfloat16(x - __bfloat162float(h));
}

__global__ void __launch_bounds__(256)
split2_kernel(const float* __restrict__ X, __nv_bfloat16* __restrict__ hi,
              __nv_bfloat16* __restrict__ lo)
{
    size_t i = (size_t)blockIdx.x * 256 + threadIdx.x;
    float4 v = ((const float4*)X)[i];
    bh4 h, l;
    split1(v.x, h.a, l.a); split1(v.y, h.b, l.b);
    split1(v.z, h.c, l.c); split1(v.w, h.d, l.d);
    ((bh4*)hi)[i] = h;
    ((bh4*)lo)[i] = l;
}

__global__ void __launch_bounds__(256)
split_both_kernel(const float* __restrict__ in,
                  __nv_bfloat16* __restrict__ ohi, __nv_bfloat16* __restrict__ olo,
                  __nv_bfloat16* __restrict__ thi, __nv_bfloat16* __restrict__ tlo)
{
    __shared__ float t[32][33];
    const int b = blockIdx.z;
    const float* I = in + (size_t)b * TT;
    const int x = blockIdx.x * 32 + threadIdx.x;
    const int y = blockIdx.y * 32 + threadIdx.y;
    const size_t ob = (size_t)b * TT;
    #pragma unroll
    for (int j = 0; j < 32; j += 8) {
        float v = I[(size_t)(y + j) * 1024 + x];
        t[threadIdx.y + j][threadIdx.x] = v;
        __nv_bfloat16 h, l; split1(v, h, l);
        ohi[ob + (size_t)(y + j) * 1024 + x] = h;
        olo[ob + (size_t)(y + j) * 1024 + x] = l;
    }
    __syncthreads();
    const int ox = blockIdx.y * 32 + threadIdx.x;
    const int oy = blockIdx.x * 32 + threadIdx.y;
    #pragma unroll
    for (int j = 0; j < 32; j += 8) {
        float v = t[threadIdx.x][threadIdx.y + j];
        __nv_bfloat16 h, l; split1(v, h, l);
        thi[ob + (size_t)(oy + j) * 1024 + ox] = h;
        tlo[ob + (size_t)(oy + j) * 1024 + ox] = l;
    }
}

__global__ void __launch_bounds__(256)
transpose_split_kernel(const float* __restrict__ in, __nv_bfloat16* __restrict__ ohi,
                       __nv_bfloat16* __restrict__ olo)
{
    __shared__ float t[32][33];
    const int b = blockIdx.z;
    const float* I = in + (size_t)b * TT;
    const int x = blockIdx.x * 32 + threadIdx.x;
    const int y = blockIdx.y * 32 + threadIdx.y;
    #pragma unroll
    for (int j = 0; j < 32; j += 8)
        t[threadIdx.y + j][threadIdx.x] = I[(size_t)(y + j) * 1024 + x];
    __syncthreads();
    const int ox = blockIdx.y * 32 + threadIdx.x;
    const int oy = blockIdx.x * 32 + threadIdx.y;
    const size_t ob = (size_t)b * TT;
    #pragma unroll
    for (int j = 0; j < 32; j += 8) {
        float v = t[threadIdx.x][threadIdx.y + j];
        __nv_bfloat16 h, l; split1(v, h, l);
        ohi[ob + (size_t)(oy + j) * 1024 + ox] = h;
        olo[ob + (size_t)(oy + j) * 1024 + ox] = l;
    }
}

// Fused column softmax (over Tp = rows of S[b]) + exp + bf16 split.
__global__ void __launch_bounds__(256)
softmax_exp_split(const float* __restrict__ S,
                  __nv_bfloat16* __restrict__ Ehi, __nv_bfloat16* __restrict__ Elo)
{
    __shared__ float sm[8][32], sz[8][32];
    __shared__ float fm[32], fz[32];
    const int b = blockIdx.y;
    const int c = (threadIdx.x & 31);
    const int g = threadIdx.x >> 5;
    const int col = blockIdx.x * 32 + c;
    const float* Sb = S + (size_t)b * TT + col;

    float m = -1e30f, z = 0.f;
    #pragma unroll 4
    for (int r = g; r < 1024; r += 8) {
        float x = Sb[(size_t)r << 10];
        if (x > m) { z = z * __expf(m - x) + 1.f; m = x; }
        else       { z += __expf(x - m); }
    }
    sm[g][c] = m; sz[g][c] = z;
    __syncthreads();
    if (threadIdx.x < 32) {
        float M = sm[0][c];
        #pragma unroll
        for (int i = 1; i < 8; i++) M = fmaxf(M, sm[i][c]);
        float Z = 0.f;
        #pragma unroll
        for (int i = 0; i < 8; i++) Z += sz[i][c] * __expf(sm[i][c] - M);
        fm[c] = M; fz[c] = 1.0f / Z;
    }
    __syncthreads();
    const float Mf = fm[c], Rf = fz[c];
    __nv_bfloat16* eh = Ehi + (size_t)b * TT + col;
    __nv_bfloat16* el = Elo + (size_t)b * TT + col;
    #pragma unroll 4
    for (int r = g; r < 1024; r += 8) {
        float x = Sb[(size_t)r << 10];
        float w = __expf(x - Mf) * Rf;
        __nv_bfloat16 h, l; split1(w, h, l);
        eh[(size_t)r << 10] = h;
        el[(size_t)r << 10] = l;
    }
}

// ---------------- launcher ----------------
extern "C" void kernel_launch(void* const* d_in, const int* in_sizes, int n_in,
                              void* d_out, int out_size)
{
    const float* q = (const float*)d_in[0];
    const float* p = (const float*)d_in[1];
    const float* W = (const float*)d_in[2];
    float* out = (float*)d_out;

    __nv_bfloat16 *qhi, *qlo, *phi, *plo, *qThi, *qTlo, *Wthi, *Wtlo, *pWhi, *pWlo, *Ehi, *Elo;
    float *S;
    cudaGetSymbolAddress((void**)&qhi, g_qhi);   cudaGetSymbolAddress((void**)&qlo, g_qlo);
    cudaGetSymbolAddress((void**)&phi, g_phi);   cudaGetSymbolAddress((void**)&plo, g_plo);
    cudaGetSymbolAddress((void**)&qThi, g_qThi); cudaGetSymbolAddress((void**)&qTlo, g_qTlo);
    cudaGetSymbolAddress((void**)&Wthi, g_Wthi); cudaGetSymbolAddress((void**)&Wtlo, g_Wtlo);
    cudaGetSymbolAddress((void**)&pWhi, g_pWhi); cudaGetSymbolAddress((void**)&pWlo, g_pWlo);
    cudaGetSymbolAddress((void**)&Ehi, g_Ehi);   cudaGetSymbolAddress((void**)&Elo, g_Elo);
    cudaGetSymbolAddress((void**)&S, g_S);

    cudaFuncSetAttribute(gemm_mma<0>, cudaFuncAttributeMaxDynamicSharedMemorySize, SMEMSZ);
    cudaFuncSetAttribute(gemm_mma<1>, cudaFuncAttributeMaxDynamicSharedMemorySize, SMEMSZ);

    const dim3 ggrid(8, 8, 16);

    split2_kernel<<<16384, 256>>>(p, phi, plo);
    split_both_kernel<<<dim3(32, 32, 16), dim3(32, 8)>>>(q, qhi, qlo, qThi, qTlo);
    transpose_split_kernel<<<dim3(32, 32, 1), dim3(32, 8)>>>(W, Wthi, Wtlo);

    // GEMM1: pW = p @ W   (B = W^T K-major), split-store
    gemm_mma<1><<<ggrid, 320, SMEMSZ>>>(phi, plo, TT, Wthi, Wtlo, 0L,
                                        nullptr, pWhi, pWlo);
    // GEMM2: S = pW @ q^T -> fp32
    gemm_mma<0><<<ggrid, 320, SMEMSZ>>>(pWhi, pWlo, TT, qhi, qlo, TT,
                                        S, nullptr, nullptr);
    // fused: column softmax stats + exp + split
    softmax_exp_split<<<dim3(32, 16), 256>>>(S, Ehi, Elo);
    // GEMM3: out = E @ q  (B = q^T K-major) -> fp32
    gemm_mma<0><<<ggrid, 320, SMEMSZ>>>(Ehi, Elo, TT, qThi, qTlo, TT,
                                        out, nullptr, nullptr);
}

// round 9
// speedup vs baseline: 1.3603x; 1.3603x over previous
#include <cuda_runtime.h>
#include <cuda_bf16.h>
#include <cstdint>

// B=16, TQ=TP=DQ=DP=1024
// out = softmax_over_Tp((p@W)@q^T) @ q, fp32 in/out.
// GEMMs: mma.sync.m16n8k16 bf16, 2-way split, 3 products (hh+hl+lh).
// 128x128x64 CTA tile, 512 threads (16 warps, 32x32 tiles), 3-stage cp.async,
// explicit fragment double-buffering (hh prefetch) in the inner loop.

static const long TT = 1048576L;

// ---------------- scratch ----------------
__device__ __nv_bfloat16 g_qhi[16777216], g_qlo[16777216];
__device__ __nv_bfloat16 g_phi[16777216], g_plo[16777216];
__device__ __nv_bfloat16 g_qThi[16777216], g_qTlo[16777216];
__device__ __nv_bfloat16 g_Wthi[1048576],  g_Wtlo[1048576];
__device__ __nv_bfloat16 g_pWhi[16777216], g_pWlo[16777216];
__device__ __nv_bfloat16 g_Ehi[16777216],  g_Elo[16777216];
__device__ float g_S[16777216];

// ---------------- asm helpers ----------------
__device__ __forceinline__ uint32_t smem_u32(const void* p) {
    uint32_t a;
    asm("{ .reg .u64 t; cvta.to.shared.u64 t, %1; cvt.u32.u64 %0, t; }" : "=r"(a) : "l"(p));
    return a;
}
__device__ __forceinline__ void cp16(uint32_t s, const void* g) {
    asm volatile("cp.async.cg.shared.global [%0], [%1], 16;" :: "r"(s), "l"(g));
}
__device__ __forceinline__ void cp_commit() { asm volatile("cp.async.commit_group;"); }
template<int N>
__device__ __forceinline__ void cp_wait() { asm volatile("cp.async.wait_group %0;" :: "n"(N)); }

__device__ __forceinline__ void ldsm4(uint32_t (&r)[4], uint32_t a) {
    asm volatile("ldmatrix.sync.aligned.m8n8.x4.shared.b16 {%0,%1,%2,%3}, [%4];"
                 : "=r"(r[0]), "=r"(r[1]), "=r"(r[2]), "=r"(r[3]) : "r"(a));
}
__device__ __forceinline__ void mma16816(float (&d)[4], const uint32_t (&a)[4],
                                         uint32_t b0, uint32_t b1) {
    asm volatile(
        "mma.sync.aligned.m16n8k16.row.col.f32.bf16.bf16.f32 "
        "{%0,%1,%2,%3}, {%4,%5,%6,%7}, {%8,%9}, {%0,%1,%2,%3};"
        : "+f"(d[0]), "+f"(d[1]), "+f"(d[2]), "+f"(d[3])
        : "r"(a[0]), "r"(a[1]), "r"(a[2]), "r"(a[3]), "r"(b0), "r"(b1));
}

// ---------------- GEMM: C[b][m][n] = sum_k A[b][m][k] * B[b][n][k] ----------------
static constexpr int MATB   = 128 * 128;   // 16KB per matrix tile (128 rows x 128B)
static constexpr int STAGEB = 4 * MATB;    // Ahi,Alo,Bhi,Blo = 64KB
static constexpr int SMEMSZ = 3 * STAGEB;  // 192KB

template<int STORE_SPLIT>
__global__ void __launch_bounds__(512, 1)
gemm_mma(const __nv_bfloat16* __restrict__ Ahi, const __nv_bfloat16* __restrict__ Alo, long sA,
         const __nv_bfloat16* __restrict__ Bhi, const __nv_bfloat16* __restrict__ Blo, long sB,
         float* __restrict__ Cf, __nv_bfloat16* __restrict__ Chi, __nv_bfloat16* __restrict__ Clo)
{
    extern __shared__ char smem[];
    const uint32_t sbase = smem_u32(smem);
    const int tid = threadIdx.x, lane = tid & 31, wid = tid >> 5;
    const int wm = wid >> 2, wn = wid & 3;        // 4x4 warp grid, 32x32 warp tiles
    const int b = blockIdx.z, m0 = blockIdx.y * 128, n0 = blockIdx.x * 128;

    const char* gA[2] = { (const char*)(Ahi + (size_t)b * sA + (size_t)m0 * 1024),
                          (const char*)(Alo + (size_t)b * sA + (size_t)m0 * 1024) };
    const char* gB[2] = { (const char*)(Bhi + (size_t)b * sB + (size_t)n0 * 1024),
                          (const char*)(Blo + (size_t)b * sB + (size_t)n0 * 1024) };

    // loader: per matrix 1024 x 16B chunks, thread handles 2 (tid, tid+512)
    const int crow[2] = { tid >> 3, (tid + 512) >> 3 };
    const int ccol = tid & 7;

    auto issue_stage = [&](int buf, int kt) {
        const uint32_t sb = sbase + buf * STAGEB;
        const size_t kb = (size_t)kt * 128;
        #pragma unroll
        for (int m = 0; m < 4; m++) {
            const char* g = (m < 2) ? gA[m] : gB[m - 2];
            const uint32_t mb = sb + m * MATB;
            #pragma unroll
            for (int t = 0; t < 2; t++) {
                const int r = crow[t];
                cp16(mb + r * 128 + ((ccol ^ (r & 7)) * 16),
                     g + (size_t)r * 2048 + kb + ccol * 16);
            }
        }
        cp_commit();
    };

    float acc[2][4][4];
    #pragma unroll
    for (int i = 0; i < 2; i++)
        #pragma unroll
        for (int j = 0; j < 4; j++)
            #pragma unroll
            for (int t = 0; t < 4; t++) acc[i][j][t] = 0.f;

    issue_stage(0, 0);
    issue_stage(1, 1);

    // ldmatrix lane addressing
    const int lrow = lane & 15, lhi = lane >> 4;
    const int swz = lrow & 7;
    uint32_t koff[4];
    #pragma unroll
    for (int ks = 0; ks < 4; ks++) koff[ks] = (uint32_t)(((ks * 2 + lhi) ^ swz) * 16);

    const uint32_t arow_off = (uint32_t)(wm * 32 + lrow) * 128;
    const uint32_t brow_off = (uint32_t)(wn * 32 + lrow) * 128;

    // fragment buffers: hh double-buffered, al/bl single
    uint32_t ahb[2][2][4], bhb[2][4][2];
    uint32_t al[2][4], bl[4][2];

    #pragma unroll 1
    for (int i = 0; i < 16; i++) {
        if (i < 15) cp_wait<1>(); else cp_wait<0>();
        __syncthreads();
        if (i + 2 < 16) issue_stage((i + 2) % 3, i + 2);

        const uint32_t sb = sbase + (i % 3) * STAGEB;
        const uint32_t sAh = sb, sAl = sb + MATB, sBh = sb + 2 * MATB, sBl = sb + 3 * MATB;

        // prologue: hh fragments for ks=0
        #pragma unroll
        for (int mi = 0; mi < 2; mi++)
            ldsm4(ahb[0][mi], sAh + arow_off + (uint32_t)(mi * 16) * 128 + koff[0]);
        #pragma unroll
        for (int nj = 0; nj < 2; nj++) {
            uint32_t r[4];
            ldsm4(r, sBh + brow_off + (uint32_t)(nj * 16) * 128 + koff[0]);
            bhb[0][2*nj][0] = r[0]; bhb[0][2*nj+1][0] = r[1];
            bhb[0][2*nj][1] = r[2]; bhb[0][2*nj+1][1] = r[3];
        }

        #pragma unroll
        for (int ks = 0; ks < 4; ks++) {
            const int cur = ks & 1, nxt = cur ^ 1;
            const uint32_t kb = koff[ks];

            // issue lo-fragment loads for this ks (consumed after hh block)
            #pragma unroll
            for (int nj = 0; nj < 2; nj++) {
                uint32_t r[4];
                ldsm4(r, sBl + brow_off + (uint32_t)(nj * 16) * 128 + kb);
                bl[2*nj][0] = r[0]; bl[2*nj+1][0] = r[1];
                bl[2*nj][1] = r[2]; bl[2*nj+1][1] = r[3];
            }
            #pragma unroll
            for (int mi = 0; mi < 2; mi++)
                ldsm4(al[mi], sAl + arow_off + (uint32_t)(mi * 16) * 128 + kb);

            // prefetch hh fragments for ks+1
            if (ks < 3) {
                const uint32_t kn = koff[ks + 1];
                #pragma unroll
                for (int mi = 0; mi < 2; mi++)
                    ldsm4(ahb[nxt][mi], sAh + arow_off + (uint32_t)(mi * 16) * 128 + kn);
                #pragma unroll
                for (int nj = 0; nj < 2; nj++) {
                    uint32_t r[4];
                    ldsm4(r, sBh + brow_off + (uint32_t)(nj * 16) * 128 + kn);
                    bhb[nxt][2*nj][0] = r[0]; bhb[nxt][2*nj+1][0] = r[1];
                    bhb[nxt][2*nj][1] = r[2]; bhb[nxt][2*nj+1][1] = r[3];
                }
            }

            // product 1: hh (fragments prefetched — no stall)
            #pragma unroll
            for (int mi = 0; mi < 2; mi++)
                #pragma unroll
                for (int ni = 0; ni < 4; ni++)
                    mma16816(acc[mi][ni], ahb[cur][mi], bhb[cur][ni][0], bhb[cur][ni][1]);
            // product 2: hl
            #pragma unroll
            for (int mi = 0; mi < 2; mi++)
                #pragma unroll
                for (int ni = 0; ni < 4; ni++)
                    mma16816(acc[mi][ni], ahb[cur][mi], bl[ni][0], bl[ni][1]);
            // product 3: lh
            #pragma unroll
            for (int mi = 0; mi < 2; mi++)
                #pragma unroll
                for (int ni = 0; ni < 4; ni++)
                    mma16816(acc[mi][ni], al[mi], bhb[cur][ni][0], bhb[cur][ni][1]);
        }
    }

    // epilogue
    const int er = m0 + wm * 32 + (lane >> 2);
    const int ec = n0 + wn * 32 + (lane & 3) * 2;
    #pragma unroll
    for (int mi = 0; mi < 2; mi++)
        #pragma unroll
        for (int ni = 0; ni < 4; ni++) {
            const int r0 = er + mi * 16, c = ec + ni * 8;
            const size_t o0 = (size_t)b * TT + (size_t)r0 * 1024 + c;
            const size_t o1 = o0 + 8 * 1024;
            if (STORE_SPLIT == 0) {
                *(float2*)(Cf + o0) = make_float2(acc[mi][ni][0], acc[mi][ni][1]);
                *(float2*)(Cf + o1) = make_float2(acc[mi][ni][2], acc[mi][ni][3]);
            } else {
                #pragma unroll
                for (int h = 0; h < 2; h++) {
                    const size_t o = h ? o1 : o0;
                    float x0 = acc[mi][ni][2*h], x1 = acc[mi][ni][2*h+1];
                    __nv_bfloat16 h0 = __float2bfloat16(x0);
                    __nv_bfloat16 h1 = __float2bfloat16(x1);
                    __nv_bfloat16 l0 = __float2bfloat16(x0 - __bfloat162float(h0));
                    __nv_bfloat16 l1 = __float2bfloat16(x1 - __bfloat162float(h1));
                    __nv_bfloat162 hp; hp.x = h0; hp.y = h1;
                    __nv_bfloat162 lp; lp.x = l0; lp.y = l1;
                    *(__nv_bfloat162*)(Chi + o) = hp;
                    *(__nv_bfloat162*)(Clo + o) = lp;
                }
            }
        }
}

// ---------------- elementwise / transpose / softmax ----------------
struct alignas(8) bh4 { __nv_bfloat16 a, b, c, d; };

__device__ __forceinline__ void split1(float x, __nv_bfloat16& h, __nv_bfloat16& l) {
    h = __float2bfloat16(x);
    l = __float2bfloat16(x - __bfloat162float(h));
}

__global__ void __launch_bounds__(256)
split2_kernel(const float* __restrict__ X, __nv_bfloat16* __restrict__ hi,
              __nv_bfloat16* __restrict__ lo)
{
    size_t i = (size_t)blockIdx.x * 256 + threadIdx.x;
    float4 v = ((const float4*)X)[i];
    bh4 h, l;
    split1(v.x, h.a, l.a); split1(v.y, h.b, l.b);
    split1(v.z, h.c, l.c); split1(v.w, h.d, l.d);
    ((bh4*)hi)[i] = h;
    ((bh4*)lo)[i] = l;
}

__global__ void __launch_bounds__(256)
split_both_kernel(const float* __restrict__ in,
                  __nv_bfloat16* __restrict__ ohi, __nv_bfloat16* __restrict__ olo,
                  __nv_bfloat16* __restrict__ thi, __nv_bfloat16* __restrict__ tlo)
{
    __shared__ float t[32][33];
    const int b = blockIdx.z;
    const float* I = in + (size_t)b * TT;
    const int x = blockIdx.x * 32 + threadIdx.x;
    const int y = blockIdx.y * 32 + threadIdx.y;
    const size_t ob = (size_t)b * TT;
    #pragma unroll
    for (int j = 0; j < 32; j += 8) {
        float v = I[(size_t)(y + j) * 1024 + x];
        t[threadIdx.y + j][threadIdx.x] = v;
        __nv_bfloat16 h, l; split1(v, h, l);
        ohi[ob + (size_t)(y + j) * 1024 + x] = h;
        olo[ob + (size_t)(y + j) * 1024 + x] = l;
    }
    __syncthreads();
    const int ox = blockIdx.y * 32 + threadIdx.x;
    const int oy = blockIdx.x * 32 + threadIdx.y;
    #pragma unroll
    for (int j = 0; j < 32; j += 8) {
        float v = t[threadIdx.x][threadIdx.y + j];
        __nv_bfloat16 h, l; split1(v, h, l);
        thi[ob + (size_t)(oy + j) * 1024 + ox] = h;
        tlo[ob + (size_t)(oy + j) * 1024 + ox] = l;
    }
}

__global__ void __launch_bounds__(256)
transpose_split_kernel(const float* __restrict__ in, __nv_bfloat16* __restrict__ ohi,
                       __nv_bfloat16* __restrict__ olo)
{
    __shared__ float t[32][33];
    const int b = blockIdx.z;
    const float* I = in + (size_t)b * TT;
    const int x = blockIdx.x * 32 + threadIdx.x;
    const int y = blockIdx.y * 32 + threadIdx.y;
    #pragma unroll
    for (int j = 0; j < 32; j += 8)
        t[threadIdx.y + j][threadIdx.x] = I[(size_t)(y + j) * 1024 + x];
    __syncthreads();
    const int ox = blockIdx.y * 32 + threadIdx.x;
    const int oy = blockIdx.x * 32 + threadIdx.y;
    const size_t ob = (size_t)b * TT;
    #pragma unroll
    for (int j = 0; j < 32; j += 8) {
        float v = t[threadIdx.x][threadIdx.y + j];
        __nv_bfloat16 h, l; split1(v, h, l);
        ohi[ob + (size_t)(oy + j) * 1024 + ox] = h;
        olo[ob + (size_t)(oy + j) * 1024 + ox] = l;
    }
}

// Fused column softmax (over Tp = rows of S[b]) + exp + bf16 split.
__global__ void __launch_bounds__(256)
softmax_exp_split(const float* __restrict__ S,
                  __nv_bfloat16* __restrict__ Ehi, __nv_bfloat16* __restrict__ Elo)
{
    __shared__ float sm[8][32], sz[8][32];
    __shared__ float fm[32], fz[32];
    const int b = blockIdx.y;
    const int c = (threadIdx.x & 31);
    const int g = threadIdx.x >> 5;
    const int col = blockIdx.x * 32 + c;
    const float* Sb = S + (size_t)b * TT + col;

    float m = -1e30f, z = 0.f;
    #pragma unroll 4
    for (int r = g; r < 1024; r += 8) {
        float x = Sb[(size_t)r << 10];
        if (x > m) { z = z * __expf(m - x) + 1.f; m = x; }
        else       { z += __expf(x - m); }
    }
    sm[g][c] = m; sz[g][c] = z;
    __syncthreads();
    if (threadIdx.x < 32) {
        float M = sm[0][c];
        #pragma unroll
        for (int i = 1; i < 8; i++) M = fmaxf(M, sm[i][c]);
        float Z = 0.f;
        #pragma unroll
        for (int i = 0; i < 8; i++) Z += sz[i][c] * __expf(sm[i][c] - M);
        fm[c] = M; fz[c] = 1.0f / Z;
    }
    __syncthreads();
    const float Mf = fm[c], Rf = fz[c];
    __nv_bfloat16* eh = Ehi + (size_t)b * TT + col;
    __nv_bfloat16* el = Elo + (size_t)b * TT + col;
    #pragma unroll 4
    for (int r = g; r < 1024; r += 8) {
        float x = Sb[(size_t)r << 10];
        float w = __expf(x - Mf) * Rf;
        __nv_bfloat16 h, l; split1(w, h, l);
        eh[(size_t)r << 10] = h;
        el[(size_t)r << 10] = l;
    }
}

// ---------------- launcher ----------------
extern "C" void kernel_launch(void* const* d_in, const int* in_sizes, int n_in,
                              void* d_out, int out_size)
{
    const float* q = (const float*)d_in[0];
    const float* p = (const float*)d_in[1];
    const float* W = (const float*)d_in[2];
    float* out = (float*)d_out;

    __nv_bfloat16 *qhi, *qlo, *phi, *plo, *qThi, *qTlo, *Wthi, *Wtlo, *pWhi, *pWlo, *Ehi, *Elo;
    float *S;
    cudaGetSymbolAddress((void**)&qhi, g_qhi);   cudaGetSymbolAddress((void**)&qlo, g_qlo);
    cudaGetSymbolAddress((void**)&phi, g_phi);   cudaGetSymbolAddress((void**)&plo, g_plo);
    cudaGetSymbolAddress((void**)&qThi, g_qThi); cudaGetSymbolAddress((void**)&qTlo, g_qTlo);
    cudaGetSymbolAddress((void**)&Wthi, g_Wthi); cudaGetSymbolAddress((void**)&Wtlo, g_Wtlo);
    cudaGetSymbolAddress((void**)&pWhi, g_pWhi); cudaGetSymbolAddress((void**)&pWlo, g_pWlo);
    cudaGetSymbolAddress((void**)&Ehi, g_Ehi);   cudaGetSymbolAddress((void**)&Elo, g_Elo);
    cudaGetSymbolAddress((void**)&S, g_S);

    cudaFuncSetAttribute(gemm_mma<0>, cudaFuncAttributeMaxDynamicSharedMemorySize, SMEMSZ);
    cudaFuncSetAttribute(gemm_mma<1>, cudaFuncAttributeMaxDynamicSharedMemorySize, SMEMSZ);

    const dim3 ggrid(8, 8, 16);

    split2_kernel<<<16384, 256>>>(p, phi, plo);
    split_both_kernel<<<dim3(32, 32, 16), dim3(32, 8)>>>(q, qhi, qlo, qThi, qTlo);
    transpose_split_kernel<<<dim3(32, 32, 1), dim3(32, 8)>>>(W, Wthi, Wtlo);

    // GEMM1: pW = p @ W   (B = W^T K-major), split-store
    gemm_mma<1><<<ggrid, 512, SMEMSZ>>>(phi, plo, TT, Wthi, Wtlo, 0L,
                                        nullptr, pWhi, pWlo);
    // GEMM2: S = pW @ q^T -> fp32
    gemm_mma<0><<<ggrid, 512, SMEMSZ>>>(pWhi, pWlo, TT, qhi, qlo, TT,
                                        S, nullptr, nullptr);
    // fused: column softmax stats + exp + split
    softmax_exp_split<<<dim3(32, 16), 256>>>(S, Ehi, Elo);
    // GEMM3: out = E @ q  (B = q^T K-major) -> fp32
    gemm_mma<0><<<ggrid, 512, SMEMSZ>>>(Ehi, Elo, TT, qThi, qTlo, TT,
                                        out, nullptr, nullptr);
}

// round 10
// speedup vs baseline: 1.4349x; 1.0548x over previous
#include <cuda_runtime.h>
#include <cuda_bf16.h>
#include <cstdint>

// B=16, TQ=TP=DQ=DP=1024
// out = softmax_over_Tp((p@W)@q^T) @ q, fp32 in/out.
// GEMMs: mma.sync.m16n8k16 bf16, 2-way split, 3 products (hh+hl+lh).
// 128x128x64 CTA tile, 512 threads (16 warps, 32x32 tiles), 3-stage cp.async.
// TRANSB=0: B K-major (NT, ldsm);  TRANSB=1: B k-row-major (NN, ldsm.trans).

static const long TT = 1048576L;

// ---------------- scratch ----------------
__device__ __nv_bfloat16 g_qhi[16777216], g_qlo[16777216];
__device__ __nv_bfloat16 g_phi[16777216], g_plo[16777216];
__device__ __nv_bfloat16 g_Whi[1048576],  g_Wlo[1048576];
__device__ __nv_bfloat16 g_pWhi[16777216], g_pWlo[16777216];
__device__ __nv_bfloat16 g_Ehi[16777216],  g_Elo[16777216];
__device__ float g_S[16777216];

// ---------------- asm helpers ----------------
__device__ __forceinline__ uint32_t smem_u32(const void* p) {
    uint32_t a;
    asm("{ .reg .u64 t; cvta.to.shared.u64 t, %1; cvt.u32.u64 %0, t; }" : "=r"(a) : "l"(p));
    return a;
}
__device__ __forceinline__ void cp16(uint32_t s, const void* g) {
    asm volatile("cp.async.cg.shared.global [%0], [%1], 16;" :: "r"(s), "l"(g));
}
__device__ __forceinline__ void cp_commit() { asm volatile("cp.async.commit_group;"); }
template<int N>
__device__ __forceinline__ void cp_wait() { asm volatile("cp.async.wait_group %0;" :: "n"(N)); }

__device__ __forceinline__ void ldsm4(uint32_t (&r)[4], uint32_t a) {
    asm volatile("ldmatrix.sync.aligned.m8n8.x4.shared.b16 {%0,%1,%2,%3}, [%4];"
                 : "=r"(r[0]), "=r"(r[1]), "=r"(r[2]), "=r"(r[3]) : "r"(a));
}
__device__ __forceinline__ void ldsm4t(uint32_t (&r)[4], uint32_t a) {
    asm volatile("ldmatrix.sync.aligned.m8n8.x4.trans.shared.b16 {%0,%1,%2,%3}, [%4];"
                 : "=r"(r[0]), "=r"(r[1]), "=r"(r[2]), "=r"(r[3]) : "r"(a));
}
__device__ __forceinline__ void mma16816(float (&d)[4], const uint32_t (&a)[4],
                                         uint32_t b0, uint32_t b1) {
    asm volatile(
        "mma.sync.aligned.m16n8k16.row.col.f32.bf16.bf16.f32 "
        "{%0,%1,%2,%3}, {%4,%5,%6,%7}, {%8,%9}, {%0,%1,%2,%3};"
        : "+f"(d[0]), "+f"(d[1]), "+f"(d[2]), "+f"(d[3])
        : "r"(a[0]), "r"(a[1]), "r"(a[2]), "r"(a[3]), "r"(b0), "r"(b1));
}

// ---------------- GEMM ----------------
// TRANSB=0: C[b][m][n] = sum_k A[b][m][k] * B[b][n][k]   (B K-major)
// TRANSB=1: C[b][m][n] = sum_k A[b][m][k] * B[b][k][n]   (B row-major over k)
static constexpr int MATB   = 128 * 128;   // 16KB per matrix tile
static constexpr int STAGEB = 4 * MATB;    // Ahi,Alo,Bhi,Blo = 64KB
static constexpr int SMEMSZ = 3 * STAGEB;  // 192KB

template<int STORE_SPLIT, int TRANSB>
__global__ void __launch_bounds__(512, 1)
gemm_mma(const __nv_bfloat16* __restrict__ Ahi, const __nv_bfloat16* __restrict__ Alo, long sA,
         const __nv_bfloat16* __restrict__ Bhi, const __nv_bfloat16* __restrict__ Blo, long sB,
         float* __restrict__ Cf, __nv_bfloat16* __restrict__ Chi, __nv_bfloat16* __restrict__ Clo)
{
    extern __shared__ char smem[];
    const uint32_t sbase = smem_u32(smem);
    const int tid = threadIdx.x, lane = tid & 31, wid = tid >> 5;
    const int wm = wid >> 2, wn = wid & 3;        // 4x4 warp grid, 32x32 warp tiles
    const int b = blockIdx.z, m0 = blockIdx.y * 128, n0 = blockIdx.x * 128;

    const char* gA[2] = { (const char*)(Ahi + (size_t)b * sA + (size_t)m0 * 1024),
                          (const char*)(Alo + (size_t)b * sA + (size_t)m0 * 1024) };
    // TRANSB=0: B rows are n (offset n0), k along row. TRANSB=1: B rows are k, n along row (offset n0*2 bytes).
    const char* gB[2] = { (const char*)(Bhi + (size_t)b * sB) + (TRANSB ? (size_t)n0 * 2 : (size_t)n0 * 2048),
                          (const char*)(Blo + (size_t)b * sB) + (TRANSB ? (size_t)n0 * 2 : (size_t)n0 * 2048) };

    // A loader (and NT B): 128 rows x 8 chunks; thread handles 2 (tid, tid+512)
    const int crow[2] = { tid >> 3, (tid + 512) >> 3 };
    const int ccol = tid & 7;
    // NN B loader: 64 rows x 16 chunks
    const int brow[2] = { tid >> 4, (tid + 512) >> 4 };
    const int bcol = tid & 15;

    auto issue_stage = [&](int buf, int kt) {
        const uint32_t sb = sbase + buf * STAGEB;
        const size_t kb = (size_t)kt * 128;   // byte offset of K64 chunk within 2048B K-major row
        #pragma unroll
        for (int m = 0; m < 2; m++) {   // A hi/lo
            const uint32_t mb = sb + m * MATB;
            #pragma unroll
            for (int t = 0; t < 2; t++) {
                const int r = crow[t];
                cp16(mb + r * 128 + ((ccol ^ (r & 7)) * 16),
                     gA[m] + (size_t)r * 2048 + kb + ccol * 16);
            }
        }
        #pragma unroll
        for (int m = 0; m < 2; m++) {   // B hi/lo
            const uint32_t mb = sb + (2 + m) * MATB;
            if (TRANSB == 0) {
                #pragma unroll
                for (int t = 0; t < 2; t++) {
                    const int r = crow[t];
                    cp16(mb + r * 128 + ((ccol ^ (r & 7)) * 16),
                         gB[m] + (size_t)r * 2048 + kb + ccol * 16);
                }
            } else {
                // 64 k-rows x 256B (128 n-cols); global row = kt*64 + r, row stride 2048B
                #pragma unroll
                for (int t = 0; t < 2; t++) {
                    const int r = brow[t];
                    cp16(mb + r * 256 + ((bcol ^ (r & 7)) * 16),
                         gB[m] + (size_t)(kt * 64 + r) * 2048 + bcol * 16);
                }
            }
        }
        cp_commit();
    };

    float acc[2][4][4];
    #pragma unroll
    for (int i = 0; i < 2; i++)
        #pragma unroll
        for (int j = 0; j < 4; j++)
            #pragma unroll
            for (int t = 0; t < 4; t++) acc[i][j][t] = 0.f;

    issue_stage(0, 0);
    issue_stage(1, 1);

    // ldmatrix lane addressing (K-major tiles: A always, B when TRANSB=0)
    const int lrow = lane & 15, lhi = lane >> 4;
    const int swz = lrow & 7;
    uint32_t koff[4];
    #pragma unroll
    for (int ks = 0; ks < 4; ks++) koff[ks] = (uint32_t)(((ks * 2 + lhi) ^ swz) * 16);

    const uint32_t arow_off = (uint32_t)(wm * 32 + lrow) * 128;
    const uint32_t brow_off = (uint32_t)(wn * 32 + lrow) * 128;   // TRANSB=0

    // TRANSB=1 ldsm.trans addressing: lane covers k-row (lane&15), n-chunk (lane>>4).
    // addr(ks, nj) = ks*4096 + tb_base[nj]; swizzle is ks-invariant (16-row stages, 8-row swizzle period).
    uint32_t tb_base[2];
    #pragma unroll
    for (int nj = 0; nj < 2; nj++) {
        const int cn = wn * 4 + nj * 2 + lhi;
        tb_base[nj] = (uint32_t)(lrow * 256 + ((cn ^ swz) * 16));
    }

    #pragma unroll 1
    for (int i = 0; i < 16; i++) {
        if (i < 15) cp_wait<1>(); else cp_wait<0>();
        __syncthreads();
        if (i + 2 < 16) issue_stage((i + 2) % 3, i + 2);

        const uint32_t sb = sbase + (i % 3) * STAGEB;
        const uint32_t sAh = sb, sAl = sb + MATB, sBh = sb + 2 * MATB, sBl = sb + 3 * MATB;

        #pragma unroll
        for (int ks = 0; ks < 4; ks++) {
            const uint32_t kb = koff[ks];
            uint32_t ah[2][4], al[2][4];
            #pragma unroll
            for (int mi = 0; mi < 2; mi++) {
                const uint32_t ro = arow_off + (uint32_t)(mi * 16) * 128 + kb;
                ldsm4(ah[mi], sAh + ro);
                ldsm4(al[mi], sAl + ro);
            }
            uint32_t bh[4][2], bl[4][2];
            if (TRANSB == 0) {
                #pragma unroll
                for (int nj = 0; nj < 2; nj++) {
                    const uint32_t ro = brow_off + (uint32_t)(nj * 16) * 128 + kb;
                    uint32_t r[4];
                    ldsm4(r, sBh + ro);
                    bh[2*nj][0] = r[0]; bh[2*nj+1][0] = r[1];
                    bh[2*nj][1] = r[2]; bh[2*nj+1][1] = r[3];
                    ldsm4(r, sBl + ro);
                    bl[2*nj][0] = r[0]; bl[2*nj+1][0] = r[1];
                    bl[2*nj][1] = r[2]; bl[2*nj+1][1] = r[3];
                }
            } else {
                #pragma unroll
                for (int nj = 0; nj < 2; nj++) {
                    const uint32_t ro = (uint32_t)(ks * 4096) + tb_base[nj];
                    uint32_t r[4];
                    ldsm4t(r, sBh + ro);
                    bh[2*nj][0] = r[0]; bh[2*nj][1] = r[1];
                    bh[2*nj+1][0] = r[2]; bh[2*nj+1][1] = r[3];
                    ldsm4t(r, sBl + ro);
                    bl[2*nj][0] = r[0]; bl[2*nj][1] = r[1];
                    bl[2*nj+1][0] = r[2]; bl[2*nj+1][1] = r[3];
                }
            }
            #pragma unroll
            for (int mi = 0; mi < 2; mi++)
                #pragma unroll
                for (int ni = 0; ni < 4; ni++) {
                    mma16816(acc[mi][ni], ah[mi], bh[ni][0], bh[ni][1]);  // hh
                    mma16816(acc[mi][ni], ah[mi], bl[ni][0], bl[ni][1]);  // hl
                    mma16816(acc[mi][ni], al[mi], bh[ni][0], bh[ni][1]);  // lh
                }
        }
    }

    // epilogue
    const int er = m0 + wm * 32 + (lane >> 2);
    const int ec = n0 + wn * 32 + (lane & 3) * 2;
    #pragma unroll
    for (int mi = 0; mi < 2; mi++)
        #pragma unroll
        for (int ni = 0; ni < 4; ni++) {
            const int r0 = er + mi * 16, c = ec + ni * 8;
            const size_t o0 = (size_t)b * TT + (size_t)r0 * 1024 + c;
            const size_t o1 = o0 + 8 * 1024;
            if (STORE_SPLIT == 0) {
                *(float2*)(Cf + o0) = make_float2(acc[mi][ni][0], acc[mi][ni][1]);
                *(float2*)(Cf + o1) = make_float2(acc[mi][ni][2], acc[mi][ni][3]);
            } else {
                #pragma unroll
                for (int h = 0; h < 2; h++) {
                    const size_t o = h ? o1 : o0;
                    float x0 = acc[mi][ni][2*h], x1 = acc[mi][ni][2*h+1];
                    __nv_bfloat16 h0 = __float2bfloat16(x0);
                    __nv_bfloat16 h1 = __float2bfloat16(x1);
                    __nv_bfloat16 l0 = __float2bfloat16(x0 - __bfloat162float(h0));
                    __nv_bfloat16 l1 = __float2bfloat16(x1 - __bfloat162float(h1));
                    __nv_bfloat162 hp; hp.x = h0; hp.y = h1;
                    __nv_bfloat162 lp; lp.x = l0; lp.y = l1;
                    *(__nv_bfloat162*)(Chi + o) = hp;
                    *(__nv_bfloat162*)(Clo + o) = lp;
                }
            }
        }
}

// ---------------- elementwise / softmax ----------------
struct alignas(8) bh4 { __nv_bfloat16 a, b, c, d; };

__device__ __forceinline__ void split1(float x, __nv_bfloat16& h, __nv_bfloat16& l) {
    h = __float2bfloat16(x);
    l = __float2bfloat16(x - __bfloat162float(h));
}

__global__ void __launch_bounds__(256)
split2_kernel(const float* __restrict__ X, __nv_bfloat16* __restrict__ hi,
              __nv_bfloat16* __restrict__ lo)
{
    size_t i = (size_t)blockIdx.x * 256 + threadIdx.x;
    float4 v = ((const float4*)X)[i];
    bh4 h, l;
    split1(v.x, h.a, l.a); split1(v.y, h.b, l.b);
    split1(v.z, h.c, l.c); split1(v.w, h.d, l.d);
    ((bh4*)hi)[i] = h;
    ((bh4*)lo)[i] = l;
}

// Fused column softmax (over Tp = rows of S[b]) + exp + bf16 split.
__global__ void __launch_bounds__(256)
softmax_exp_split(const float* __restrict__ S,
                  __nv_bfloat16* __restrict__ Ehi, __nv_bfloat16* __restrict__ Elo)
{
    __shared__ float sm[8][32], sz[8][32];
    __shared__ float fm[32], fz[32];
    const int b = blockIdx.y;
    const int c = (threadIdx.x & 31);
    const int g = threadIdx.x >> 5;
    const int col = blockIdx.x * 32 + c;
    const float* Sb = S + (size_t)b * TT + col;

    float m = -1e30f, z = 0.f;
    #pragma unroll 4
    for (int r = g; r < 1024; r += 8) {
        float x = Sb[(size_t)r << 10];
        if (x > m) { z = z * __expf(m - x) + 1.f; m = x; }
        else       { z += __expf(x - m); }
    }
    sm[g][c] = m; sz[g][c] = z;
    __syncthreads();
    if (threadIdx.x < 32) {
        float M = sm[0][c];
        #pragma unroll
        for (int i = 1; i < 8; i++) M = fmaxf(M, sm[i][c]);
        float Z = 0.f;
        #pragma unroll
        for (int i = 0; i < 8; i++) Z += sz[i][c] * __expf(sm[i][c] - M);
        fm[c] = M; fz[c] = 1.0f / Z;
    }
    __syncthreads();
    const float Mf = fm[c], Rf = fz[c];
    __nv_bfloat16* eh = Ehi + (size_t)b * TT + col;
    __nv_bfloat16* el = Elo + (size_t)b * TT + col;
    #pragma unroll 4
    for (int r = g; r < 1024; r += 8) {
        float x = Sb[(size_t)r << 10];
        float w = __expf(x - Mf) * Rf;
        __nv_bfloat16 h, l; split1(w, h, l);
        eh[(size_t)r << 10] = h;
        el[(size_t)r << 10] = l;
    }
}

// ---------------- launcher ----------------
extern "C" void kernel_launch(void* const* d_in, const int* in_sizes, int n_in,
                              void* d_out, int out_size)
{
    const float* q = (const float*)d_in[0];
    const float* p = (const float*)d_in[1];
    const float* W = (const float*)d_in[2];
    float* out = (float*)d_out;

    __nv_bfloat16 *qhi, *qlo, *phi, *plo, *Whi, *Wlo, *pWhi, *pWlo, *Ehi, *Elo;
    float *S;
    cudaGetSymbolAddress((void**)&qhi, g_qhi);   cudaGetSymbolAddress((void**)&qlo, g_qlo);
    cudaGetSymbolAddress((void**)&phi, g_phi);   cudaGetSymbolAddress((void**)&plo, g_plo);
    cudaGetSymbolAddress((void**)&Whi, g_Whi);   cudaGetSymbolAddress((void**)&Wlo, g_Wlo);
    cudaGetSymbolAddress((void**)&pWhi, g_pWhi); cudaGetSymbolAddress((void**)&pWlo, g_pWlo);
    cudaGetSymbolAddress((void**)&Ehi, g_Ehi);   cudaGetSymbolAddress((void**)&Elo, g_Elo);
    cudaGetSymbolAddress((void**)&S, g_S);

    cudaFuncSetAttribute(gemm_mma<0,0>, cudaFuncAttributeMaxDynamicSharedMemorySize, SMEMSZ);
    cudaFuncSetAttribute(gemm_mma<0,1>, cudaFuncAttributeMaxDynamicSharedMemorySize, SMEMSZ);
    cudaFuncSetAttribute(gemm_mma<1,1>, cudaFuncAttributeMaxDynamicSharedMemorySize, SMEMSZ);

    const dim3 ggrid(8, 8, 16);

    split2_kernel<<<16384, 256>>>(p, phi, plo);
    split2_kernel<<<16384, 256>>>(q, qhi, qlo);
    split2_kernel<<<1024,  256>>>(W, Whi, Wlo);

    // GEMM1 (NN): pW = p @ W, split-store
    gemm_mma<1,1><<<ggrid, 512, SMEMSZ>>>(phi, plo, TT, Whi, Wlo, 0L,
                                          nullptr, pWhi, pWlo);
    // GEMM2 (NT): S = pW @ q^T -> fp32
    gemm_mma<0,0><<<ggrid, 512, SMEMSZ>>>(pWhi, pWlo, TT, qhi, qlo, TT,
                                          S, nullptr, nullptr);
    // fused: column softmax stats + exp + split
    softmax_exp_split<<<dim3(32, 16), 256>>>(S, Ehi, Elo);
    // GEMM3 (NN): out = E @ q -> fp32
    gemm_mma<0,1><<<ggrid, 512, SMEMSZ>>>(Ehi, Elo, TT, qhi, qlo, TT,
                                          out, nullptr, nullptr);
}

// round 11
// speedup vs baseline: 1.4494x; 1.0101x over previous
#include <cuda_runtime.h>
#include <cuda_bf16.h>
#include <cstdint>

// B=16, TQ=TP=DQ=DP=1024
// out = softmax_over_Tp((p@W)@q^T) @ q, fp32 in/out.
// GEMMs: mma.sync.m16n8k16 bf16, 2-way split, 3 products (hh+hl+lh).
// All GEMMs in NN mode (B k-row-major via ldmatrix.trans), 128x128x64 CTA tile,
// 512 threads (16 warps, 32x32 tiles), 3-stage cp.async pipeline.

static const long TT = 1048576L;

// ---------------- scratch ----------------
__device__ __nv_bfloat16 g_qhi[16777216], g_qlo[16777216];
__device__ __nv_bfloat16 g_qThi[16777216], g_qTlo[16777216];
__device__ __nv_bfloat16 g_phi[16777216], g_plo[16777216];
__device__ __nv_bfloat16 g_Whi[1048576],  g_Wlo[1048576];
__device__ __nv_bfloat16 g_pWhi[16777216], g_pWlo[16777216];
__device__ __nv_bfloat16 g_Ehi[16777216],  g_Elo[16777216];
__device__ float g_S[16777216];

// ---------------- asm helpers ----------------
__device__ __forceinline__ uint32_t smem_u32(const void* p) {
    uint32_t a;
    asm("{ .reg .u64 t; cvta.to.shared.u64 t, %1; cvt.u32.u64 %0, t; }" : "=r"(a) : "l"(p));
    return a;
}
__device__ __forceinline__ void cp16(uint32_t s, const void* g) {
    asm volatile("cp.async.cg.shared.global [%0], [%1], 16;" :: "r"(s), "l"(g));
}
__device__ __forceinline__ void cp_commit() { asm volatile("cp.async.commit_group;"); }
template<int N>
__device__ __forceinline__ void cp_wait() { asm volatile("cp.async.wait_group %0;" :: "n"(N)); }

__device__ __forceinline__ void ldsm4(uint32_t (&r)[4], uint32_t a) {
    asm volatile("ldmatrix.sync.aligned.m8n8.x4.shared.b16 {%0,%1,%2,%3}, [%4];"
                 : "=r"(r[0]), "=r"(r[1]), "=r"(r[2]), "=r"(r[3]) : "r"(a));
}
__device__ __forceinline__ void ldsm4t(uint32_t (&r)[4], uint32_t a) {
    asm volatile("ldmatrix.sync.aligned.m8n8.x4.trans.shared.b16 {%0,%1,%2,%3}, [%4];"
                 : "=r"(r[0]), "=r"(r[1]), "=r"(r[2]), "=r"(r[3]) : "r"(a));
}
__device__ __forceinline__ void mma16816(float (&d)[4], const uint32_t (&a)[4],
                                         uint32_t b0, uint32_t b1) {
    asm volatile(
        "mma.sync.aligned.m16n8k16.row.col.f32.bf16.bf16.f32 "
        "{%0,%1,%2,%3}, {%4,%5,%6,%7}, {%8,%9}, {%0,%1,%2,%3};"
        : "+f"(d[0]), "+f"(d[1]), "+f"(d[2]), "+f"(d[3])
        : "r"(a[0]), "r"(a[1]), "r"(a[2]), "r"(a[3]), "r"(b0), "r"(b1));
}

// ---------------- GEMM (NN): C[b][m][n] = sum_k A[b][m][k] * B[b][k][n] ----------------
static constexpr int MATB   = 128 * 128;   // 16KB per matrix tile
static constexpr int STAGEB = 4 * MATB;    // Ahi,Alo,Bhi,Blo = 64KB
static constexpr int SMEMSZ = 3 * STAGEB;  // 192KB

template<int STORE_SPLIT>
__global__ void __launch_bounds__(512, 1)
gemm_mma(const __nv_bfloat16* __restrict__ Ahi, const __nv_bfloat16* __restrict__ Alo, long sA,
         const __nv_bfloat16* __restrict__ Bhi, const __nv_bfloat16* __restrict__ Blo, long sB,
         float* __restrict__ Cf, __nv_bfloat16* __restrict__ Chi, __nv_bfloat16* __restrict__ Clo)
{
    extern __shared__ char smem[];
    const uint32_t sbase = smem_u32(smem);
    const int tid = threadIdx.x, lane = tid & 31, wid = tid >> 5;
    const int wm = wid >> 2, wn = wid & 3;        // 4x4 warp grid, 32x32 warp tiles
    const int b = blockIdx.z, m0 = blockIdx.y * 128, n0 = blockIdx.x * 128;

    const char* gA[2] = { (const char*)(Ahi + (size_t)b * sA + (size_t)m0 * 1024),
                          (const char*)(Alo + (size_t)b * sA + (size_t)m0 * 1024) };
    // B rows are k, n along row (offset n0*2 bytes), row stride 2048B
    const char* gB[2] = { (const char*)(Bhi + (size_t)b * sB) + (size_t)n0 * 2,
                          (const char*)(Blo + (size_t)b * sB) + (size_t)n0 * 2 };

    // A loader: 128 rows x 8 chunks; thread handles 2 (tid, tid+512)
    const int crow[2] = { tid >> 3, (tid + 512) >> 3 };
    const int ccol = tid & 7;
    // B loader: 64 k-rows x 16 chunks
    const int brow[2] = { tid >> 4, (tid + 512) >> 4 };
    const int bcol = tid & 15;

    auto issue_stage = [&](int buf, int kt) {
        const uint32_t sb = sbase + buf * STAGEB;
        const size_t kb = (size_t)kt * 128;
        #pragma unroll
        for (int m = 0; m < 2; m++) {   // A hi/lo
            const uint32_t mb = sb + m * MATB;
            #pragma unroll
            for (int t = 0; t < 2; t++) {
                const int r = crow[t];
                cp16(mb + r * 128 + ((ccol ^ (r & 7)) * 16),
                     gA[m] + (size_t)r * 2048 + kb + ccol * 16);
            }
        }
        #pragma unroll
        for (int m = 0; m < 2; m++) {   // B hi/lo: 64 k-rows x 256B
            const uint32_t mb = sb + (2 + m) * MATB;
            #pragma unroll
            for (int t = 0; t < 2; t++) {
                const int r = brow[t];
                cp16(mb + r * 256 + ((bcol ^ (r & 7)) * 16),
                     gB[m] + (size_t)(kt * 64 + r) * 2048 + bcol * 16);
            }
        }
        cp_commit();
    };

    float acc[2][4][4];
    #pragma unroll
    for (int i = 0; i < 2; i++)
        #pragma unroll
        for (int j = 0; j < 4; j++)
            #pragma unroll
            for (int t = 0; t < 4; t++) acc[i][j][t] = 0.f;

    issue_stage(0, 0);
    issue_stage(1, 1);

    // ldmatrix lane addressing
    const int lrow = lane & 15, lhi = lane >> 4;
    const int swz = lrow & 7;
    uint32_t koff[4];
    #pragma unroll
    for (int ks = 0; ks < 4; ks++) koff[ks] = (uint32_t)(((ks * 2 + lhi) ^ swz) * 16);

    const uint32_t arow_off = (uint32_t)(wm * 32 + lrow) * 128;

    // B trans addressing: lane covers k-row (lane&15), n-chunk (lane>>4)
    uint32_t tb_base[2];
    #pragma unroll
    for (int nj = 0; nj < 2; nj++) {
        const int cn = wn * 4 + nj * 2 + lhi;
        tb_base[nj] = (uint32_t)(lrow * 256 + ((cn ^ swz) * 16));
    }

    #pragma unroll 1
    for (int i = 0; i < 16; i++) {
        if (i < 15) cp_wait<1>(); else cp_wait<0>();
        __syncthreads();
        if (i + 2 < 16) issue_stage((i + 2) % 3, i + 2);

        const uint32_t sb = sbase + (i % 3) * STAGEB;
        const uint32_t sAh = sb, sAl = sb + MATB, sBh = sb + 2 * MATB, sBl = sb + 3 * MATB;

        #pragma unroll
        for (int ks = 0; ks < 4; ks++) {
            const uint32_t kb = koff[ks];
            uint32_t ah[2][4], al[2][4];
            #pragma unroll
            for (int mi = 0; mi < 2; mi++) {
                const uint32_t ro = arow_off + (uint32_t)(mi * 16) * 128 + kb;
                ldsm4(ah[mi], sAh + ro);
                ldsm4(al[mi], sAl + ro);
            }
            uint32_t bh[4][2], bl[4][2];
            #pragma unroll
            for (int nj = 0; nj < 2; nj++) {
                const uint32_t ro = (uint32_t)(ks * 4096) + tb_base[nj];
                uint32_t r[4];
                ldsm4t(r, sBh + ro);
                bh[2*nj][0] = r[0]; bh[2*nj][1] = r[1];
                bh[2*nj+1][0] = r[2]; bh[2*nj+1][1] = r[3];
                ldsm4t(r, sBl + ro);
                bl[2*nj][0] = r[0]; bl[2*nj][1] = r[1];
                bl[2*nj+1][0] = r[2]; bl[2*nj+1][1] = r[3];
            }
            #pragma unroll
            for (int mi = 0; mi < 2; mi++)
                #pragma unroll
                for (int ni = 0; ni < 4; ni++) {
                    mma16816(acc[mi][ni], ah[mi], bh[ni][0], bh[ni][1]);  // hh
                    mma16816(acc[mi][ni], ah[mi], bl[ni][0], bl[ni][1]);  // hl
                    mma16816(acc[mi][ni], al[mi], bh[ni][0], bh[ni][1]);  // lh
                }
        }
    }

    // epilogue
    const int er = m0 + wm * 32 + (lane >> 2);
    const int ec = n0 + wn * 32 + (lane & 3) * 2;
    #pragma unroll
    for (int mi = 0; mi < 2; mi++)
        #pragma unroll
        for (int ni = 0; ni < 4; ni++) {
            const int r0 = er + mi * 16, c = ec + ni * 8;
            const size_t o0 = (size_t)b * TT + (size_t)r0 * 1024 + c;
            const size_t o1 = o0 + 8 * 1024;
            if (STORE_SPLIT == 0) {
                *(float2*)(Cf + o0) = make_float2(acc[mi][ni][0], acc[mi][ni][1]);
                *(float2*)(Cf + o1) = make_float2(acc[mi][ni][2], acc[mi][ni][3]);
            } else {
                #pragma unroll
                for (int h = 0; h < 2; h++) {
                    const size_t o = h ? o1 : o0;
                    float x0 = acc[mi][ni][2*h], x1 = acc[mi][ni][2*h+1];
                    __nv_bfloat16 h0 = __float2bfloat16(x0);
                    __nv_bfloat16 h1 = __float2bfloat16(x1);
                    __nv_bfloat16 l0 = __float2bfloat16(x0 - __bfloat162float(h0));
                    __nv_bfloat16 l1 = __float2bfloat16(x1 - __bfloat162float(h1));
                    __nv_bfloat162 hp; hp.x = h0; hp.y = h1;
                    __nv_bfloat162 lp; lp.x = l0; lp.y = l1;
                    *(__nv_bfloat162*)(Chi + o) = hp;
                    *(__nv_bfloat162*)(Clo + o) = lp;
                }
            }
        }
}

// ---------------- elementwise / transpose / softmax ----------------
struct alignas(8) bh4 { __nv_bfloat16 a, b, c, d; };

__device__ __forceinline__ void split1(float x, __nv_bfloat16& h, __nv_bfloat16& l) {
    h = __float2bfloat16(x);
    l = __float2bfloat16(x - __bfloat162float(h));
}

__global__ void __launch_bounds__(256)
split2_kernel(const float* __restrict__ X, __nv_bfloat16* __restrict__ hi,
              __nv_bfloat16* __restrict__ lo)
{
    size_t i = (size_t)blockIdx.x * 256 + threadIdx.x;
    float4 v = ((const float4*)X)[i];
    bh4 h, l;
    split1(v.x, h.a, l.a); split1(v.y, h.b, l.b);
    split1(v.z, h.c, l.c); split1(v.w, h.d, l.d);
    ((bh4*)hi)[i] = h;
    ((bh4*)lo)[i] = l;
}

// reads a 32x32 tile once; writes straight split (ohi/olo) and transposed split (thi/tlo)
__global__ void __launch_bounds__(256)
split_both_kernel(const float* __restrict__ in,
                  __nv_bfloat16* __restrict__ ohi, __nv_bfloat16* __restrict__ olo,
                  __nv_bfloat16* __restrict__ thi, __nv_bfloat16* __restrict__ tlo)
{
    __shared__ float t[32][33];
    const int b = blockIdx.z;
    const float* I = in + (size_t)b * TT;
    const int x = blockIdx.x * 32 + threadIdx.x;
    const int y = blockIdx.y * 32 + threadIdx.y;
    const size_t ob = (size_t)b * TT;
    #pragma unroll
    for (int j = 0; j < 32; j += 8) {
        float v = I[(size_t)(y + j) * 1024 + x];
        t[threadIdx.y + j][threadIdx.x] = v;
        __nv_bfloat16 h, l; split1(v, h, l);
        ohi[ob + (size_t)(y + j) * 1024 + x] = h;
        olo[ob + (size_t)(y + j) * 1024 + x] = l;
    }
    __syncthreads();
    const int ox = blockIdx.y * 32 + threadIdx.x;
    const int oy = blockIdx.x * 32 + threadIdx.y;
    #pragma unroll
    for (int j = 0; j < 32; j += 8) {
        float v = t[threadIdx.x][threadIdx.y + j];
        __nv_bfloat16 h, l; split1(v, h, l);
        thi[ob + (size_t)(oy + j) * 1024 + ox] = h;
        tlo[ob + (size_t)(oy + j) * 1024 + ox] = l;
    }
}

// Fused column softmax (over Tp = rows of S[b]) + exp + bf16 split.
__global__ void __launch_bounds__(256)
softmax_exp_split(const float* __restrict__ S,
                  __nv_bfloat16* __restrict__ Ehi, __nv_bfloat16* __restrict__ Elo)
{
    __shared__ float sm[8][32], sz[8][32];
    __shared__ float fm[32], fz[32];
    const int b = blockIdx.y;
    const int c = (threadIdx.x & 31);
    const int g = threadIdx.x >> 5;
    const int col = blockIdx.x * 32 + c;
    const float* Sb = S + (size_t)b * TT + col;

    float m = -1e30f, z = 0.f;
    #pragma unroll 4
    for (int r = g; r < 1024; r += 8) {
        float x = Sb[(size_t)r << 10];
        if (x > m) { z = z * __expf(m - x) + 1.f; m = x; }
        else       { z += __expf(x - m); }
    }
    sm[g][c] = m; sz[g][c] = z;
    __syncthreads();
    if (threadIdx.x < 32) {
        float M = sm[0][c];
        #pragma unroll
        for (int i = 1; i < 8; i++) M = fmaxf(M, sm[i][c]);
        float Z = 0.f;
        #pragma unroll
        for (int i = 0; i < 8; i++) Z += sz[i][c] * __expf(sm[i][c] - M);
        fm[c] = M; fz[c] = 1.0f / Z;
    }
    __syncthreads();
    const float Mf = fm[c], Rf = fz[c];
    __nv_bfloat16* eh = Ehi + (size_t)b * TT + col;
    __nv_bfloat16* el = Elo + (size_t)b * TT + col;
    #pragma unroll 4
    for (int r = g; r < 1024; r += 8) {
        float x = Sb[(size_t)r << 10];
        float w = __expf(x - Mf) * Rf;
        __nv_bfloat16 h, l; split1(w, h, l);
        eh[(size_t)r << 10] = h;
        el[(size_t)r << 10] = l;
    }
}

// ---------------- launcher ----------------
extern "C" void kernel_launch(void* const* d_in, const int* in_sizes, int n_in,
                              void* d_out, int out_size)
{
    const float* q = (const float*)d_in[0];
    const float* p = (const float*)d_in[1];
    const float* W = (const float*)d_in[2];
    float* out = (float*)d_out;

    __nv_bfloat16 *qhi, *qlo, *qThi, *qTlo, *phi, *plo, *Whi, *Wlo, *pWhi, *pWlo, *Ehi, *Elo;
    float *S;
    cudaGetSymbolAddress((void**)&qhi, g_qhi);   cudaGetSymbolAddress((void**)&qlo, g_qlo);
    cudaGetSymbolAddress((void**)&qThi, g_qThi); cudaGetSymbolAddress((void**)&qTlo, g_qTlo);
    cudaGetSymbolAddress((void**)&phi, g_phi);   cudaGetSymbolAddress((void**)&plo, g_plo);
    cudaGetSymbolAddress((void**)&Whi, g_Whi);   cudaGetSymbolAddress((void**)&Wlo, g_Wlo);
    cudaGetSymbolAddress((void**)&pWhi, g_pWhi); cudaGetSymbolAddress((void**)&pWlo, g_pWlo);
    cudaGetSymbolAddress((void**)&Ehi, g_Ehi);   cudaGetSymbolAddress((void**)&Elo, g_Elo);
    cudaGetSymbolAddress((void**)&S, g_S);

    cudaFuncSetAttribute(gemm_mma<0>, cudaFuncAttributeMaxDynamicSharedMemorySize, SMEMSZ);
    cudaFuncSetAttribute(gemm_mma<1>, cudaFuncAttributeMaxDynamicSharedMemorySize, SMEMSZ);

    const dim3 ggrid(8, 8, 16);

    split2_kernel<<<16384, 256>>>(p, phi, plo);
    split_both_kernel<<<dim3(32, 32, 16), dim3(32, 8)>>>(q, qhi, qlo, qThi, qTlo);
    split2_kernel<<<1024,  256>>>(W, Whi, Wlo);

    // GEMM1 (NN): pW = p @ W, split-store
    gemm_mma<1><<<ggrid, 512, SMEMSZ>>>(phi, plo, TT, Whi, Wlo, 0L,
                                        nullptr, pWhi, pWlo);
    // GEMM2 (NN): S = pW @ q^T, B = qT [Dq, Tq] k-row-major -> fp32
    gemm_mma<0><<<ggrid, 512, SMEMSZ>>>(pWhi, pWlo, TT, qThi, qTlo, TT,
                                        S, nullptr, nullptr);
    // fused: column softmax stats + exp + split
    softmax_exp_split<<<dim3(32, 16), 256>>>(S, Ehi, Elo);
    // GEMM3 (NN): out = E @ q -> fp32
    gemm_mma<0><<<ggrid, 512, SMEMSZ>>>(Ehi, Elo, TT, qhi, qlo, TT,
                                        out, nullptr, nullptr);
}